// round 11
// baseline (speedup 1.0000x reference)
#include <cuda_runtime.h>
#include <math.h>

#define NROWS 2048
#define DIN   128
#define HDIM  256
#define DEMB  64
#define KSPLIT 8
#define KCHUNK (NROWS / KSPLIT)   // 256

// ---------------- scratch (no allocation allowed) ----------------
__device__ float g_outx[NROWS * HDIM];            // relu(x@W0+b0)   2 MB
__device__ float g_emb[NROWS * DEMB];             // relu(outx@W1+b1)
__device__ float g_xlast[NROWS * DIN];            // x@W2+b2
__device__ float g_sq[NROWS];                     // ||emb_i||^2
__device__ float g_degpart[32 * NROWS];           // per column-tile row sums of A
__device__ float g_deg[NROWS];                    // row degree
__device__ float g_outpart[KSPLIT * NROWS * DIN]; // split-K partials of A@xlast (8 MB)

// ================= generic 64x64x16 SGEMM, optional bias + relu =================
// C[M,NC] = A[M,K] @ B[K,NC] (+bias) (relu?)   M%64==0, NC%64==0, K%16==0
__global__ __launch_bounds__(256) void sgemm_bias(
    const float* __restrict__ A, const float* __restrict__ B,
    const float* __restrict__ bias, float* __restrict__ C,
    int M, int NC, int K, int do_relu)
{
    __shared__ float As[16][64];   // [k][m]
    __shared__ float Bs[16][64];   // [k][n]
    const int tid = threadIdx.x;
    const int tx = tid & 15, ty = tid >> 4;
    const int row0 = blockIdx.y * 64;
    const int col0 = blockIdx.x * 64;

    const int arow = tid >> 2;            // 0..63
    const int acol = (tid & 3) * 4;       // 0,4,8,12
    const int brow = tid >> 4;            // 0..15
    const int bcol = (tid & 15) * 4;      // 0..60

    float acc[4][4] = {};
    for (int k0 = 0; k0 < K; k0 += 16) {
        float4 av = *(const float4*)&A[(size_t)(row0 + arow) * K + k0 + acol];
        float4 bv = *(const float4*)&B[(size_t)(k0 + brow) * NC + col0 + bcol];
        As[acol + 0][arow] = av.x;
        As[acol + 1][arow] = av.y;
        As[acol + 2][arow] = av.z;
        As[acol + 3][arow] = av.w;
        *(float4*)&Bs[brow][bcol] = bv;
        __syncthreads();
#pragma unroll
        for (int k = 0; k < 16; k++) {
            float a[4], b[4];
#pragma unroll
            for (int i = 0; i < 4; i++) a[i] = As[k][ty * 4 + i];
#pragma unroll
            for (int j = 0; j < 4; j++) b[j] = Bs[k][tx * 4 + j];
#pragma unroll
            for (int i = 0; i < 4; i++)
#pragma unroll
                for (int j = 0; j < 4; j++)
                    acc[i][j] = fmaf(a[i], b[j], acc[i][j]);
        }
        __syncthreads();
    }
#pragma unroll
    for (int i = 0; i < 4; i++) {
        int r = row0 + ty * 4 + i;
        float4 v;
        float* vv = (float*)&v;
#pragma unroll
        for (int j = 0; j < 4; j++) {
            float t = acc[i][j];
            if (bias) t += bias[col0 + tx * 4 + j];
            if (do_relu) t = fmaxf(t, 0.0f);
            vv[j] = t;
        }
        *(float4*)&C[(size_t)r * NC + col0 + tx * 4] = v;
    }
}

// ================= sq[i] = sum_k emb[i][k]^2 =================
__global__ void sq_kernel() {
    int r = blockIdx.x * blockDim.x + threadIdx.x;
    if (r >= NROWS) return;
    const float4* e = (const float4*)(g_emb + (size_t)r * DEMB);
    float acc = 0.f;
#pragma unroll
    for (int i = 0; i < DEMB / 4; i++) {
        float4 v = e[i];
        acc = fmaf(v.x, v.x, acc);
        acc = fmaf(v.y, v.y, acc);
        acc = fmaf(v.z, v.z, acc);
        acc = fmaf(v.w, v.w, acc);
    }
    g_sq[r] = acc;
}

// ================= adjacency tile kernel =================
// A[i,j] = sigmoid((1+temp)*(2*emb_i.emb_j - sq_i - sq_j) + (5+theta)) + (i==j)
// writes A row-major, and deterministic per-(column-tile) row-sum partials.
__global__ __launch_bounds__(256) void adj_kernel(
    float* __restrict__ adj, const float* __restrict__ temp,
    const float* __restrict__ theta)
{
    __shared__ float Ei[64][65];
    __shared__ float Ej[64][65];
    __shared__ float ssqi[64];
    __shared__ float ssqj[64];
    __shared__ float red[64][17];

    const int tid = threadIdx.x;
    const int bi = blockIdx.y;   // row tile
    const int bj = blockIdx.x;   // col tile

#pragma unroll
    for (int t = 0; t < 4; t++) {
        int idx = tid + t * 256;          // 0..1023
        int r = idx >> 4;                 // 0..63
        int c = (idx & 15) * 4;           // 0..60
        float4 vi = *(const float4*)&g_emb[(size_t)(bi * 64 + r) * DEMB + c];
        float4 vj = *(const float4*)&g_emb[(size_t)(bj * 64 + r) * DEMB + c];
        Ei[r][c + 0] = vi.x; Ei[r][c + 1] = vi.y; Ei[r][c + 2] = vi.z; Ei[r][c + 3] = vi.w;
        Ej[r][c + 0] = vj.x; Ej[r][c + 1] = vj.y; Ej[r][c + 2] = vj.z; Ej[r][c + 3] = vj.w;
    }
    if (tid < 64) ssqi[tid] = g_sq[bi * 64 + tid];
    else if (tid < 128) ssqj[tid - 64] = g_sq[bj * 64 + (tid - 64)];
    __syncthreads();

    const int tx = tid & 15, ty = tid >> 4;
    float acc[4][4] = {};
#pragma unroll 4
    for (int k = 0; k < 64; k++) {
        float a[4], b[4];
#pragma unroll
        for (int i = 0; i < 4; i++) a[i] = Ei[ty * 4 + i][k];
#pragma unroll
        for (int j = 0; j < 4; j++) b[j] = Ej[tx * 4 + j][k];
#pragma unroll
        for (int i = 0; i < 4; i++)
#pragma unroll
            for (int j = 0; j < 4; j++)
                acc[i][j] = fmaf(a[i], b[j], acc[i][j]);
    }

    const float c1 = 1.0f + temp[0];
    const float c0 = 5.0f + theta[0];

#pragma unroll
    for (int i = 0; i < 4; i++) {
        int gi = bi * 64 + ty * 4 + i;
        float rowsum = 0.f;
        float4 v;
        float* vv = (float*)&v;
#pragma unroll
        for (int j = 0; j < 4; j++) {
            int gj = bj * 64 + tx * 4 + j;
            float dist = 2.0f * acc[i][j] - ssqi[ty * 4 + i] - ssqj[tx * 4 + j];
            float z = fmaf(c1, dist, c0);
            float p = __fdividef(1.0f, 1.0f + __expf(-z));
            if (gi == gj) p += 1.0f;
            vv[j] = p;
            rowsum += p;
        }
        *(float4*)&adj[(size_t)gi * NROWS + bj * 64 + tx * 4] = v;
        red[ty * 4 + i][tx] = rowsum;
    }
    __syncthreads();
    if (tid < 64) {
        float s = 0.f;
#pragma unroll
        for (int t = 0; t < 16; t++) s += red[tid][t];
        g_degpart[(size_t)bj * NROWS + bi * 64 + tid] = s;
    }
}

// ================= deg[r] = sum over 32 column-tile partials =================
__global__ void deg_reduce() {
    int r = blockIdx.x * blockDim.x + threadIdx.x;
    if (r >= NROWS) return;
    float s = 0.f;
#pragma unroll
    for (int b = 0; b < 32; b++) s += g_degpart[(size_t)b * NROWS + r];
    g_deg[r] = s;
}

// ================= split-K partial GEMM: A(2048x2048) @ xlast(2048x128) =================
__global__ __launch_bounds__(256) void sgemm_part(
    const float* __restrict__ A, const float* __restrict__ B)
{
    __shared__ float As[16][64];
    __shared__ float Bs[16][64];
    const int tid = threadIdx.x;
    const int tx = tid & 15, ty = tid >> 4;
    const int row0 = blockIdx.y * 64;
    const int col0 = blockIdx.x * 64;     // 0 or 64 (NC=128)
    const int kbase = blockIdx.z * KCHUNK;

    const int arow = tid >> 2;
    const int acol = (tid & 3) * 4;
    const int brow = tid >> 4;
    const int bcol = (tid & 15) * 4;

    float acc[4][4] = {};
    for (int k0 = kbase; k0 < kbase + KCHUNK; k0 += 16) {
        float4 av = *(const float4*)&A[(size_t)(row0 + arow) * NROWS + k0 + acol];
        float4 bv = *(const float4*)&B[(size_t)(k0 + brow) * DIN + col0 + bcol];
        As[acol + 0][arow] = av.x;
        As[acol + 1][arow] = av.y;
        As[acol + 2][arow] = av.z;
        As[acol + 3][arow] = av.w;
        *(float4*)&Bs[brow][bcol] = bv;
        __syncthreads();
#pragma unroll
        for (int k = 0; k < 16; k++) {
            float a[4], b[4];
#pragma unroll
            for (int i = 0; i < 4; i++) a[i] = As[k][ty * 4 + i];
#pragma unroll
            for (int j = 0; j < 4; j++) b[j] = Bs[k][tx * 4 + j];
#pragma unroll
            for (int i = 0; i < 4; i++)
#pragma unroll
                for (int j = 0; j < 4; j++)
                    acc[i][j] = fmaf(a[i], b[j], acc[i][j]);
        }
        __syncthreads();
    }
    float* Cp = g_outpart + (size_t)blockIdx.z * (NROWS * DIN);
#pragma unroll
    for (int i = 0; i < 4; i++) {
        int r = row0 + ty * 4 + i;
        float4 v;
        float* vv = (float*)&v;
#pragma unroll
        for (int j = 0; j < 4; j++) vv[j] = acc[i][j];
        *(float4*)&Cp[(size_t)r * DIN + col0 + tx * 4] = v;
    }
}

// ================= final: out = relu( (sum_k partials) / deg ) =================
__global__ void final_kernel(float* __restrict__ out) {
    int idx = blockIdx.x * blockDim.x + threadIdx.x;
    if (idx >= NROWS * DIN) return;
    float s = 0.f;
#pragma unroll
    for (int p = 0; p < KSPLIT; p++) s += g_outpart[(size_t)p * (NROWS * DIN) + idx];
    int row = idx / DIN;
    float v = s / g_deg[row];
    out[idx] = fmaxf(v, 0.0f);
}

// =====================================================================
extern "C" void kernel_launch(void* const* d_in, const int* in_sizes, int n_in,
                              void* d_out, int out_size) {
    const float* x     = (const float*)d_in[0];
    // d_in[1] = adj (unused, only its shape matters in the reference)
    const float* W0    = (const float*)d_in[2];
    const float* b0    = (const float*)d_in[3];
    const float* W1    = (const float*)d_in[4];
    const float* b1    = (const float*)d_in[5];
    const float* W2    = (const float*)d_in[6];
    const float* b2    = (const float*)d_in[7];
    const float* temp  = (const float*)d_in[8];
    const float* theta = (const float*)d_in[9];

    float* out_main = (float*)d_out;                 // [2048,128]
    float* adj_out  = (float*)d_out + NROWS * DIN;   // [2048,2048] flattened

    void *p_outx, *p_emb, *p_xlast;
    cudaGetSymbolAddress(&p_outx,  g_outx);
    cudaGetSymbolAddress(&p_emb,   g_emb);
    cudaGetSymbolAddress(&p_xlast, g_xlast);

    // layer 0: outx = relu(x @ W0 + b0)   [2048,256]
    sgemm_bias<<<dim3(HDIM / 64, NROWS / 64), 256>>>(
        x, W0, b0, (float*)p_outx, NROWS, HDIM, DIN, 1);
    // layer 1: emb = relu(outx @ W1 + b1) [2048,64]
    sgemm_bias<<<dim3(DEMB / 64, NROWS / 64), 256>>>(
        (const float*)p_outx, W1, b1, (float*)p_emb, NROWS, DEMB, HDIM, 1);
    // last layer on original x: xlast = x @ W2 + b2 [2048,128]
    sgemm_bias<<<dim3(DIN / 64, NROWS / 64), 256>>>(
        x, W2, b2, (float*)p_xlast, NROWS, DIN, DIN, 0);

    // squared norms of emb rows
    sq_kernel<<<NROWS / 256, 256>>>();

    // adjacency A = sigmoid(...) + I, written straight into d_out; row-sum partials
    adj_kernel<<<dim3(NROWS / 64, NROWS / 64), 256>>>(adj_out, temp, theta);

    // deg = row sums
    deg_reduce<<<NROWS / 256, 256>>>();

    // A @ xlast, split-K into 8 deterministic partials
    sgemm_part<<<dim3(DIN / 64, NROWS / 64, KSPLIT), 256>>>(adj_out, (const float*)p_xlast);

    // out = relu((A@xlast)/deg)
    final_kernel<<<(NROWS * DIN) / 256, 256>>>(out_main);
}

// round 15
// speedup vs baseline: 1.0067x; 1.0067x over previous
#include <cuda_runtime.h>
#include <math.h>

#define NROWS 2048
#define DIN   128
#define HDIM  256
#define DEMB  64
#define KSPLIT 8
#define KCHUNK (NROWS / KSPLIT)   // 256

// ---------------- scratch (no allocation allowed) ----------------
__device__ float g_outx[NROWS * HDIM];            // relu(x@W0+b0)   2 MB
__device__ float g_emb[NROWS * DEMB];             // relu(outx@W1+b1)
__device__ float g_xlast[NROWS * DIN];            // x@W2+b2
__device__ float g_sq[NROWS];                     // ||emb_i||^2
__device__ float g_degpart[32 * NROWS];           // per column-tile row sums of A
__device__ float g_deg[NROWS];                    // row degree
__device__ float g_outpart[KSPLIT * NROWS * DIN]; // split-K partials of A@xlast (8 MB)

// ================= generic 64x64x16 SGEMM, optional bias + relu =================
// C[M,NC] = A[M,K] @ B[K,NC] (+bias) (relu?)   M%64==0, NC%64==0, K%16==0
__global__ __launch_bounds__(256) void sgemm_bias(
    const float* __restrict__ A, const float* __restrict__ B,
    const float* __restrict__ bias, float* __restrict__ C,
    int M, int NC, int K, int do_relu)
{
    __shared__ float As[16][64];   // [k][m]
    __shared__ float Bs[16][64];   // [k][n]
    const int tid = threadIdx.x;
    const int tx = tid & 15, ty = tid >> 4;
    const int row0 = blockIdx.y * 64;
    const int col0 = blockIdx.x * 64;

    const int arow = tid >> 2;            // 0..63
    const int acol = (tid & 3) * 4;       // 0,4,8,12
    const int brow = tid >> 4;            // 0..15
    const int bcol = (tid & 15) * 4;      // 0..60

    float acc[4][4] = {};
    for (int k0 = 0; k0 < K; k0 += 16) {
        float4 av = *(const float4*)&A[(size_t)(row0 + arow) * K + k0 + acol];
        float4 bv = *(const float4*)&B[(size_t)(k0 + brow) * NC + col0 + bcol];
        As[acol + 0][arow] = av.x;
        As[acol + 1][arow] = av.y;
        As[acol + 2][arow] = av.z;
        As[acol + 3][arow] = av.w;
        *(float4*)&Bs[brow][bcol] = bv;
        __syncthreads();
#pragma unroll
        for (int k = 0; k < 16; k++) {
            float a[4], b[4];
#pragma unroll
            for (int i = 0; i < 4; i++) a[i] = As[k][ty * 4 + i];
#pragma unroll
            for (int j = 0; j < 4; j++) b[j] = Bs[k][tx * 4 + j];
#pragma unroll
            for (int i = 0; i < 4; i++)
#pragma unroll
                for (int j = 0; j < 4; j++)
                    acc[i][j] = fmaf(a[i], b[j], acc[i][j]);
        }
        __syncthreads();
    }
#pragma unroll
    for (int i = 0; i < 4; i++) {
        int r = row0 + ty * 4 + i;
        float4 v;
        float* vv = (float*)&v;
#pragma unroll
        for (int j = 0; j < 4; j++) {
            float t = acc[i][j];
            if (bias) t += bias[col0 + tx * 4 + j];
            if (do_relu) t = fmaxf(t, 0.0f);
            vv[j] = t;
        }
        *(float4*)&C[(size_t)r * NC + col0 + tx * 4] = v;
    }
}

// ================= sq[i] = sum_k emb[i][k]^2 =================
__global__ void sq_kernel() {
    int r = blockIdx.x * blockDim.x + threadIdx.x;
    if (r >= NROWS) return;
    const float4* e = (const float4*)(g_emb + (size_t)r * DEMB);
    float acc = 0.f;
#pragma unroll
    for (int i = 0; i < DEMB / 4; i++) {
        float4 v = e[i];
        acc = fmaf(v.x, v.x, acc);
        acc = fmaf(v.y, v.y, acc);
        acc = fmaf(v.z, v.z, acc);
        acc = fmaf(v.w, v.w, acc);
    }
    g_sq[r] = acc;
}

// ================= adjacency tile kernel =================
// A[i,j] = sigmoid((1+temp)*(2*emb_i.emb_j - sq_i - sq_j) + (5+theta)) + (i==j)
// writes A row-major, and deterministic per-(column-tile) row-sum partials.
__global__ __launch_bounds__(256) void adj_kernel(
    float* __restrict__ adj, const float* __restrict__ temp,
    const float* __restrict__ theta)
{
    __shared__ float Ei[64][65];
    __shared__ float Ej[64][65];
    __shared__ float ssqi[64];
    __shared__ float ssqj[64];
    __shared__ float red[64][17];

    const int tid = threadIdx.x;
    const int bi = blockIdx.y;   // row tile
    const int bj = blockIdx.x;   // col tile

#pragma unroll
    for (int t = 0; t < 4; t++) {
        int idx = tid + t * 256;          // 0..1023
        int r = idx >> 4;                 // 0..63
        int c = (idx & 15) * 4;           // 0..60
        float4 vi = *(const float4*)&g_emb[(size_t)(bi * 64 + r) * DEMB + c];
        float4 vj = *(const float4*)&g_emb[(size_t)(bj * 64 + r) * DEMB + c];
        Ei[r][c + 0] = vi.x; Ei[r][c + 1] = vi.y; Ei[r][c + 2] = vi.z; Ei[r][c + 3] = vi.w;
        Ej[r][c + 0] = vj.x; Ej[r][c + 1] = vj.y; Ej[r][c + 2] = vj.z; Ej[r][c + 3] = vj.w;
    }
    if (tid < 64) ssqi[tid] = g_sq[bi * 64 + tid];
    else if (tid < 128) ssqj[tid - 64] = g_sq[bj * 64 + (tid - 64)];
    __syncthreads();

    const int tx = tid & 15, ty = tid >> 4;
    float acc[4][4] = {};
#pragma unroll 4
    for (int k = 0; k < 64; k++) {
        float a[4], b[4];
#pragma unroll
        for (int i = 0; i < 4; i++) a[i] = Ei[ty * 4 + i][k];
#pragma unroll
        for (int j = 0; j < 4; j++) b[j] = Ej[tx * 4 + j][k];
#pragma unroll
        for (int i = 0; i < 4; i++)
#pragma unroll
            for (int j = 0; j < 4; j++)
                acc[i][j] = fmaf(a[i], b[j], acc[i][j]);
    }

    const float c1 = 1.0f + temp[0];
    const float c0 = 5.0f + theta[0];

#pragma unroll
    for (int i = 0; i < 4; i++) {
        int gi = bi * 64 + ty * 4 + i;
        float rowsum = 0.f;
        float4 v;
        float* vv = (float*)&v;
#pragma unroll
        for (int j = 0; j < 4; j++) {
            int gj = bj * 64 + tx * 4 + j;
            float dist = 2.0f * acc[i][j] - ssqi[ty * 4 + i] - ssqj[tx * 4 + j];
            float z = fmaf(c1, dist, c0);
            float p = __fdividef(1.0f, 1.0f + __expf(-z));
            if (gi == gj) p += 1.0f;
            vv[j] = p;
            rowsum += p;
        }
        *(float4*)&adj[(size_t)gi * NROWS + bj * 64 + tx * 4] = v;
        red[ty * 4 + i][tx] = rowsum;
    }
    __syncthreads();
    if (tid < 64) {
        float s = 0.f;
#pragma unroll
        for (int t = 0; t < 16; t++) s += red[tid][t];
        g_degpart[(size_t)bj * NROWS + bi * 64 + tid] = s;
    }
}

// ================= deg[r] = sum over 32 column-tile partials =================
__global__ void deg_reduce() {
    int r = blockIdx.x * blockDim.x + threadIdx.x;
    if (r >= NROWS) return;
    float s = 0.f;
#pragma unroll
    for (int b = 0; b < 32; b++) s += g_degpart[(size_t)b * NROWS + r];
    g_deg[r] = s;
}

// ================= split-K partial GEMM: A(2048x2048) @ xlast(2048x128) =================
__global__ __launch_bounds__(256) void sgemm_part(
    const float* __restrict__ A, const float* __restrict__ B)
{
    __shared__ float As[16][64];
    __shared__ float Bs[16][64];
    const int tid = threadIdx.x;
    const int tx = tid & 15, ty = tid >> 4;
    const int row0 = blockIdx.y * 64;
    const int col0 = blockIdx.x * 64;     // 0 or 64 (NC=128)
    const int kbase = blockIdx.z * KCHUNK;

    const int arow = tid >> 2;
    const int acol = (tid & 3) * 4;
    const int brow = tid >> 4;
    const int bcol = (tid & 15) * 4;

    float acc[4][4] = {};
    for (int k0 = kbase; k0 < kbase + KCHUNK; k0 += 16) {
        float4 av = *(const float4*)&A[(size_t)(row0 + arow) * NROWS + k0 + acol];
        float4 bv = *(const float4*)&B[(size_t)(k0 + brow) * DIN + col0 + bcol];
        As[acol + 0][arow] = av.x;
        As[acol + 1][arow] = av.y;
        As[acol + 2][arow] = av.z;
        As[acol + 3][arow] = av.w;
        *(float4*)&Bs[brow][bcol] = bv;
        __syncthreads();
#pragma unroll
        for (int k = 0; k < 16; k++) {
            float a[4], b[4];
#pragma unroll
            for (int i = 0; i < 4; i++) a[i] = As[k][ty * 4 + i];
#pragma unroll
            for (int j = 0; j < 4; j++) b[j] = Bs[k][tx * 4 + j];
#pragma unroll
            for (int i = 0; i < 4; i++)
#pragma unroll
                for (int j = 0; j < 4; j++)
                    acc[i][j] = fmaf(a[i], b[j], acc[i][j]);
        }
        __syncthreads();
    }
    float* Cp = g_outpart + (size_t)blockIdx.z * (NROWS * DIN);
#pragma unroll
    for (int i = 0; i < 4; i++) {
        int r = row0 + ty * 4 + i;
        float4 v;
        float* vv = (float*)&v;
#pragma unroll
        for (int j = 0; j < 4; j++) vv[j] = acc[i][j];
        *(float4*)&Cp[(size_t)r * DIN + col0 + tx * 4] = v;
    }
}

// ================= final: out = relu( (sum_k partials) / deg ) =================
__global__ void final_kernel(float* __restrict__ out) {
    int idx = blockIdx.x * blockDim.x + threadIdx.x;
    if (idx >= NROWS * DIN) return;
    float s = 0.f;
#pragma unroll
    for (int p = 0; p < KSPLIT; p++) s += g_outpart[(size_t)p * (NROWS * DIN) + idx];
    int row = idx / DIN;
    float v = s / g_deg[row];
    out[idx] = fmaxf(v, 0.0f);
}

// =====================================================================
extern "C" void kernel_launch(void* const* d_in, const int* in_sizes, int n_in,
                              void* d_out, int out_size) {
    const float* x     = (const float*)d_in[0];
    // d_in[1] = adj (unused, only its shape matters in the reference)
    const float* W0    = (const float*)d_in[2];
    const float* b0    = (const float*)d_in[3];
    const float* W1    = (const float*)d_in[4];
    const float* b1    = (const float*)d_in[5];
    const float* W2    = (const float*)d_in[6];
    const float* b2    = (const float*)d_in[7];
    const float* temp  = (const float*)d_in[8];
    const float* theta = (const float*)d_in[9];

    float* out_main = (float*)d_out;                 // [2048,128]
    float* adj_out  = (float*)d_out + NROWS * DIN;   // [2048,2048] flattened

    void *p_outx, *p_emb, *p_xlast;
    cudaGetSymbolAddress(&p_outx,  g_outx);
    cudaGetSymbolAddress(&p_emb,   g_emb);
    cudaGetSymbolAddress(&p_xlast, g_xlast);

    // layer 0: outx = relu(x @ W0 + b0)   [2048,256]
    sgemm_bias<<<dim3(HDIM / 64, NROWS / 64), 256>>>(
        x, W0, b0, (float*)p_outx, NROWS, HDIM, DIN, 1);
    // layer 1: emb = relu(outx @ W1 + b1) [2048,64]
    sgemm_bias<<<dim3(DEMB / 64, NROWS / 64), 256>>>(
        (const float*)p_outx, W1, b1, (float*)p_emb, NROWS, DEMB, HDIM, 1);
    // last layer on original x: xlast = x @ W2 + b2 [2048,128]
    sgemm_bias<<<dim3(DIN / 64, NROWS / 64), 256>>>(
        x, W2, b2, (float*)p_xlast, NROWS, DIN, DIN, 0);

    // squared norms of emb rows
    sq_kernel<<<NROWS / 256, 256>>>();

    // adjacency A = sigmoid(...) + I, written straight into d_out; row-sum partials
    adj_kernel<<<dim3(NROWS / 64, NROWS / 64), 256>>>(adj_out, temp, theta);

    // deg = row sums
    deg_reduce<<<NROWS / 256, 256>>>();

    // A @ xlast, split-K into 8 deterministic partials
    sgemm_part<<<dim3(DIN / 64, NROWS / 64, KSPLIT), 256>>>(adj_out, (const float*)p_xlast);

    // out = relu((A@xlast)/deg)
    final_kernel<<<(NROWS * DIN) / 256, 256>>>(out_main);
}